// round 16
// baseline (speedup 1.0000x reference)
#include <cuda_runtime.h>
#include <math.h>
#include <float.h>
#include <stdint.h>

// Problem constants
#define B_ 8
#define T_ 512
#define D_ 256
#define S_ 64
#define P_ 1024
#define R_ 12
#define N1 (R_ * D_)   // 3072: columns of GEMM1 output, n = r*256 + e

// Scratch (device globals — no allocation allowed)
__device__ float g_pA_hi[B_ * S_ * D_];         // tf32-rounded pooled, hi part
__device__ float g_pA_lo[B_ * S_ * D_];         // tf32 lo residual
__device__ float g_L[B_ * S_ * 2 * R_];         // [bs][h*12+r]
__device__ float g_T1hi[B_ * S_ * N1];          // tf32 hi of T1 (6.3 MB)
__device__ float g_T1lo[B_ * S_ * N1];          // tf32 lo residual (6.3 MB)
__device__ float g_wb_hi[R_ * D_ * D_];         // tf32 hi of W_bilinear (3 MB)
__device__ float g_wb_lo[R_ * D_ * D_];         // tf32 lo residual     (3 MB)

__device__ __forceinline__ float tf32r(float x) {
    uint32_t u;
    asm("cvt.rna.tf32.f32 %0, %1;" : "=r"(u) : "f"(x));
    return __uint_as_float(u);
}

#define MMA_TF32(C, A, Bv)                                                   \
    asm volatile(                                                            \
        "mma.sync.aligned.m16n8k8.row.col.f32.tf32.tf32.f32 "                \
        "{%0,%1,%2,%3}, {%4,%5,%6,%7}, {%8,%9}, {%0,%1,%2,%3};"              \
        : "+f"(C[0]), "+f"(C[1]), "+f"(C[2]), "+f"(C[3])                     \
        : "r"(A[0]), "r"(A[1]), "r"(A[2]), "r"(A[3]), "r"(Bv[0]), "r"(Bv[1]))

// ---------------------------------------------------------------------------
// Kernel 1: ragged span max-pool + per-span linear terms.
// Max loop 4-way unrolled: 4 independent LDGs in flight (was a serial
// LDG->FMAX chain, ~600 cyc/step). fmax is associative -> bit-identical.
// ---------------------------------------------------------------------------
__global__ __launch_bounds__(256)
void pool_kernel(const float* __restrict__ enc,
                 const float* __restrict__ Wl,   // [2D, R] row-major
                 const int* __restrict__ starts,
                 const int* __restrict__ lens) {
    __shared__ float sp[D_];
    __shared__ float red[8 * 24];

    int bs  = blockIdx.x;          // b*64 + s
    int b   = bs >> 6;
    int tid = threadIdx.x;
    int warp = tid >> 5, lane = tid & 31;

    int st = starts[bs];
    int en = st + lens[bs] + 1;    // exclusive, >= st+1
    if (en > T_) en = T_;

    const float* p = enc + ((size_t)b * T_ + st) * D_ + tid;
    float m = -FLT_MAX;
    int t = st;
    for (; t + 4 <= en; t += 4) {
        float a0 = p[0];
        float a1 = p[D_];
        float a2 = p[2 * D_];
        float a3 = p[3 * D_];
        m = fmaxf(m, fmaxf(fmaxf(a0, a1), fmaxf(a2, a3)));
        p += 4 * D_;
    }
    for (; t < en; ++t) { m = fmaxf(m, *p); p += D_; }

    float hi = tf32r(m);
    g_pA_hi[bs * D_ + tid] = hi;
    g_pA_lo[bs * D_ + tid] = tf32r(m - hi);
    sp[tid] = m;
    __syncthreads();

    // lane o = h*12 + r (o < 24 active): warp w sweeps its 32 d-values.
    if (lane < 24) {
        int h = (lane >= 12);
        int r = lane - h * 12;
        const float* wp = Wl + h * (D_ * R_) + r;
        int d0 = warp * 32;
        float sum = 0.f;
#pragma unroll
        for (int dd = 0; dd < 32; ++dd) {
            int d = d0 + dd;
            sum += sp[d] * wp[d * R_];
        }
        red[warp * 24 + lane] = sum;
    }
    __syncthreads();

    if (tid < 24) {
        float s = 0.f;
#pragma unroll
        for (int wp8 = 0; wp8 < 8; ++wp8) s += red[wp8 * 24 + tid];
        g_L[bs * (2 * R_) + tid] = s;
    }
}

// ---------------------------------------------------------------------------
// Kernel 1b: split W_bilinear into tf32 hi/lo. (proven R13 form)
// ---------------------------------------------------------------------------
__global__ __launch_bounds__(256)
void split_wb_kernel(const float* __restrict__ Wb) {
    int idx = blockIdx.x * 256 + threadIdx.x;     // 0..65535
    const float4* src = (const float4*)Wb;
    float4* dhi = (float4*)g_wb_hi;
    float4* dlo = (float4*)g_wb_lo;
#pragma unroll
    for (int i = 0; i < 3; ++i) {
        int j = idx + i * 65536;
        float4 v = src[j];
        float4 h, l;
        h.x = tf32r(v.x); l.x = tf32r(v.x - h.x);
        h.y = tf32r(v.y); l.y = tf32r(v.y - h.y);
        h.z = tf32r(v.z); l.z = tf32r(v.z - h.z);
        h.w = tf32r(v.w); l.w = tf32r(v.w - h.w);
        dhi[j] = h;
        dlo[j] = l;
    }
}

// ---------------------------------------------------------------------------
// Kernel 2: GEMM1 on tensor cores (3xTF32), byte-identical to R14/R15 form.
// ---------------------------------------------------------------------------
#define A_PITCH 36
#define B_PITCH 68
#define ASZ (64 * A_PITCH)          // floats
#define BSZ (32 * B_PITCH)
#define STAGE_F (2 * ASZ + 2 * BSZ) // 8960 floats = 35840 B
#define GEMM1_SMEM (2 * STAGE_F * 4)

__global__ __launch_bounds__(256)
void gemm1_kernel() {
    extern __shared__ float smem[];

    int tid = threadIdx.x;
    int wid = tid >> 5, lane = tid & 31;
    int g = lane >> 2, c = lane & 3;
    int warp_m = wid >> 2;            // 0..1 -> m offset *32
    int warp_n = wid & 3;             // 0..3 -> n offset *16

    int m0 = blockIdx.y * 64;
    int n0 = blockIdx.x * 64;
    int r  = n0 >> 8;
    int e0 = n0 & 255;

    const float* pAhi = g_pA_hi;
    const float* pAlo = g_pA_lo;
    const float* wbh = g_wb_hi + (size_t)r * (D_ * D_) + e0;
    const float* wbl = g_wb_lo + (size_t)r * (D_ * D_) + e0;

    unsigned sbase = (unsigned)__cvta_generic_to_shared(smem);

    float acc[2][2][4] = {};

    auto issue_stage = [&](int s, int k0) {
        unsigned st = sbase + (unsigned)(s * STAGE_F * 4);
#pragma unroll
        for (int i = 0; i < 2; ++i) {
            int op = tid + i * 256;          // 0..511
            int row = op >> 3, ch = op & 7;  // A: 64 rows x 8 chunks
            unsigned da = st + (unsigned)((row * A_PITCH + ch * 4) * 4);
            const float* sa = pAhi + (size_t)(m0 + row) * D_ + k0 + ch * 4;
            asm volatile("cp.async.cg.shared.global [%0], [%1], 16;"
                         :: "r"(da), "l"(sa) : "memory");
            unsigned da2 = da + (unsigned)(ASZ * 4);
            const float* sa2 = pAlo + (size_t)(m0 + row) * D_ + k0 + ch * 4;
            asm volatile("cp.async.cg.shared.global [%0], [%1], 16;"
                         :: "r"(da2), "l"(sa2) : "memory");
            int rk = op >> 4, chb = op & 15; // B: 32 k-rows x 16 chunks
            unsigned db = st + (unsigned)((2 * ASZ + rk * B_PITCH + chb * 4) * 4);
            const float* sb = wbh + (size_t)(k0 + rk) * D_ + chb * 4;
            asm volatile("cp.async.cg.shared.global [%0], [%1], 16;"
                         :: "r"(db), "l"(sb) : "memory");
            unsigned db2 = db + (unsigned)(BSZ * 4);
            const float* sb2 = wbl + (size_t)(k0 + rk) * D_ + chb * 4;
            asm volatile("cp.async.cg.shared.global [%0], [%1], 16;"
                         :: "r"(db2), "l"(sb2) : "memory");
        }
        asm volatile("cp.async.commit_group;" ::: "memory");
    };

    issue_stage(0, 0);
    asm volatile("cp.async.wait_group 0;" ::: "memory");
    __syncthreads();

#pragma unroll
    for (int it = 0; it < 8; ++it) {
        int s = it & 1;
        if (it < 7) issue_stage(1 - s, (it + 1) * 32);

        const float* Ah = smem + s * STAGE_F;
        const float* Al = Ah + ASZ;
        const float* Bh = smem + s * STAGE_F + 2 * ASZ;
        const float* Bl = Bh + BSZ;

#pragma unroll
        for (int k8 = 0; k8 < 4; ++k8) {
            int kc = k8 * 8 + c;
            uint32_t ah[2][4], al[2][4], bh[2][2], bl[2][2];
#pragma unroll
            for (int mi = 0; mi < 2; ++mi) {
                int rb = warp_m * 32 + mi * 16 + g;
                ah[mi][0] = __float_as_uint(Ah[rb * A_PITCH + kc]);
                ah[mi][1] = __float_as_uint(Ah[(rb + 8) * A_PITCH + kc]);
                ah[mi][2] = __float_as_uint(Ah[rb * A_PITCH + kc + 4]);
                ah[mi][3] = __float_as_uint(Ah[(rb + 8) * A_PITCH + kc + 4]);
                al[mi][0] = __float_as_uint(Al[rb * A_PITCH + kc]);
                al[mi][1] = __float_as_uint(Al[(rb + 8) * A_PITCH + kc]);
                al[mi][2] = __float_as_uint(Al[rb * A_PITCH + kc + 4]);
                al[mi][3] = __float_as_uint(Al[(rb + 8) * A_PITCH + kc + 4]);
            }
#pragma unroll
            for (int ni = 0; ni < 2; ++ni) {
                int nb = warp_n * 16 + ni * 8 + g;
                bh[ni][0] = __float_as_uint(Bh[kc * B_PITCH + nb]);
                bh[ni][1] = __float_as_uint(Bh[(kc + 4) * B_PITCH + nb]);
                bl[ni][0] = __float_as_uint(Bl[kc * B_PITCH + nb]);
                bl[ni][1] = __float_as_uint(Bl[(kc + 4) * B_PITCH + nb]);
            }
#pragma unroll
            for (int mi = 0; mi < 2; ++mi)
#pragma unroll
                for (int ni = 0; ni < 2; ++ni) {
                    MMA_TF32(acc[mi][ni], ah[mi], bh[ni]);
                    MMA_TF32(acc[mi][ni], ah[mi], bl[ni]);
                    MMA_TF32(acc[mi][ni], al[mi], bh[ni]);
                }
        }

        if (it < 7) asm volatile("cp.async.wait_group 0;" ::: "memory");
        __syncthreads();
    }

    // Epilogue: split T1 into tf32 hi/lo and store both.
#pragma unroll
    for (int mi = 0; mi < 2; ++mi)
#pragma unroll
        for (int ni = 0; ni < 2; ++ni) {
            int row = m0 + warp_m * 32 + mi * 16 + g;
            int col = n0 + warp_n * 16 + ni * 8 + 2 * c;
            float v0 = acc[mi][ni][0], v1 = acc[mi][ni][1];
            float v2 = acc[mi][ni][2], v3 = acc[mi][ni][3];
            float h0 = tf32r(v0), h1 = tf32r(v1), h2 = tf32r(v2), h3 = tf32r(v3);
            *(float2*)&g_T1hi[(size_t)row * N1 + col] = make_float2(h0, h1);
            *(float2*)&g_T1lo[(size_t)row * N1 + col] =
                make_float2(tf32r(v0 - h0), tf32r(v1 - h1));
            *(float2*)&g_T1hi[(size_t)(row + 8) * N1 + col] = make_float2(h2, h3);
            *(float2*)&g_T1lo[(size_t)(row + 8) * N1 + col] =
                make_float2(tf32r(v2 - h2), tf32r(v3 - h3));
        }
}

// ---------------------------------------------------------------------------
// Kernel 3: GEMM2 on tensor cores (3xTF32) + fused score epilogue,
// s-split x2: 192 blocks (bid = b*24 + r*2 + sh), each computes the 32x64
// G sub-tile G[sh*32 + 0..31][t] over k=256. Same fragment math as R15;
// per-output accumulation order unchanged (bit-identical G values).
// Stage = A(32x36 hi+lo) + B(64x36 hi+lo) = 27.6 KB; depth-3 pipeline
// (83 KB) -> 2 blocks/SM co-residency; 192 blocks cover all 148 SMs
// (R15: 96 blocks @147 KB = 1 block/SM on 96 SMs, no latency overlap).
// Epilogue gathers pairs whose head falls in this block's s-half.
// ---------------------------------------------------------------------------
#define G2_PITCH 36
#define G2_AT (32 * G2_PITCH)         // 1152 floats per A tile
#define G2_BT (64 * G2_PITCH)         // 2304 floats per B tile
#define G2_STAGE (2 * G2_AT + 2 * G2_BT)  // 6912 floats = 27648 B
#define G2_NSTAGE 3
#define GEMM2_SMEM (G2_NSTAGE * G2_STAGE * 4) // 82944 B

__global__ __launch_bounds__(256)
void gemm2_kernel(const float* __restrict__ bias,
                  const int* __restrict__ ph,
                  const int* __restrict__ pt,
                  float* __restrict__ out) {
    extern __shared__ float smem[];

    int bid = blockIdx.x;                 // b*24 + r*2 + sh
    int b   = bid / 24;
    int rem = bid - b * 24;
    int r   = rem >> 1;
    int sh  = rem & 1;
    int s0g = sh * 32;                    // global s offset of this half

    int tid = threadIdx.x;
    int wid = tid >> 5, lane = tid & 31;
    int g = lane >> 2, c = lane & 3;
    int warp_n = wid;                     // 0..7 -> t offset *8

    const float* Ahg = g_T1hi + ((size_t)b * S_ + s0g) * N1 + r * D_; // +s*N1
    const float* Alg = g_T1lo + ((size_t)b * S_ + s0g) * N1 + r * D_;
    const float* Bhg = g_pA_hi + (size_t)b * S_ * D_;                 // +t*256
    const float* Blg = g_pA_lo + (size_t)b * S_ * D_;

    unsigned sbase = (unsigned)__cvta_generic_to_shared(smem);

    float acc[2][4] = {};

    // Per stage: A 32x8 chunks x2 (512 ops) + B 64x8 x2 (1024) = 1536 ops,
    // 6 per thread.
    auto issue_stage = [&](int s, int k0) {
        unsigned st = sbase + (unsigned)(s * G2_STAGE * 4);
        {
            int row = tid >> 3, ch = tid & 7;          // A: rows 0..31
            unsigned d0 = st + (unsigned)((row * G2_PITCH + ch * 4) * 4);
            const float* s0 = Ahg + (size_t)row * N1 + k0 + ch * 4;
            asm volatile("cp.async.cg.shared.global [%0], [%1], 16;"
                         :: "r"(d0), "l"(s0) : "memory");
            unsigned d1 = d0 + (unsigned)(G2_AT * 4);
            const float* s1 = Alg + (size_t)row * N1 + k0 + ch * 4;
            asm volatile("cp.async.cg.shared.global [%0], [%1], 16;"
                         :: "r"(d1), "l"(s1) : "memory");
        }
#pragma unroll
        for (int i = 0; i < 2; ++i) {
            int op = tid + i * 256;
            int row = op >> 3, ch = op & 7;            // B: rows 0..63
            unsigned d2 = st + (unsigned)((2 * G2_AT + row * G2_PITCH + ch * 4) * 4);
            const float* s2 = Bhg + (size_t)row * D_ + k0 + ch * 4;
            asm volatile("cp.async.cg.shared.global [%0], [%1], 16;"
                         :: "r"(d2), "l"(s2) : "memory");
            unsigned d3 = d2 + (unsigned)(G2_BT * 4);
            const float* s3 = Blg + (size_t)row * D_ + k0 + ch * 4;
            asm volatile("cp.async.cg.shared.global [%0], [%1], 16;"
                         :: "r"(d3), "l"(s3) : "memory");
        }
        asm volatile("cp.async.commit_group;" ::: "memory");
    };

    // Prologue: fill 2 of 3 stages.
    issue_stage(0, 0);
    issue_stage(1, 32);
    asm volatile("cp.async.wait_group 1;" ::: "memory");   // stage 0 ready
    __syncthreads();

    int slot = 0;
#pragma unroll
    for (int it = 0; it < 8; ++it) {
        if (it + 2 < 8) {
            int ns = slot + 2; if (ns >= 3) ns -= 3;
            issue_stage(ns, (it + 2) * 32);
        }

        const float* Ah = smem + slot * G2_STAGE;
        const float* Al = Ah + G2_AT;
        const float* Bh = Al + G2_AT;
        const float* Bl = Bh + G2_BT;

#pragma unroll
        for (int k8 = 0; k8 < 4; ++k8) {
            int kc = k8 * 8 + c;
            uint32_t ah[2][4], al[2][4], bh[2], bl[2];
#pragma unroll
            for (int mi = 0; mi < 2; ++mi) {
                int rb = mi * 16 + g;
                ah[mi][0] = __float_as_uint(Ah[rb * G2_PITCH + kc]);
                ah[mi][1] = __float_as_uint(Ah[(rb + 8) * G2_PITCH + kc]);
                ah[mi][2] = __float_as_uint(Ah[rb * G2_PITCH + kc + 4]);
                ah[mi][3] = __float_as_uint(Ah[(rb + 8) * G2_PITCH + kc + 4]);
                al[mi][0] = __float_as_uint(Al[rb * G2_PITCH + kc]);
                al[mi][1] = __float_as_uint(Al[(rb + 8) * G2_PITCH + kc]);
                al[mi][2] = __float_as_uint(Al[rb * G2_PITCH + kc + 4]);
                al[mi][3] = __float_as_uint(Al[(rb + 8) * G2_PITCH + kc + 4]);
            }
            {
                int nb = warp_n * 8 + g;
                bh[0] = __float_as_uint(Bh[nb * G2_PITCH + kc]);
                bh[1] = __float_as_uint(Bh[nb * G2_PITCH + kc + 4]);
                bl[0] = __float_as_uint(Bl[nb * G2_PITCH + kc]);
                bl[1] = __float_as_uint(Bl[nb * G2_PITCH + kc + 4]);
            }
#pragma unroll
            for (int mi = 0; mi < 2; ++mi) {
                MMA_TF32(acc[mi], ah[mi], bh);
                MMA_TF32(acc[mi], ah[mi], bl);
                MMA_TF32(acc[mi], al[mi], bh);
            }
        }

        asm volatile("cp.async.wait_group 1;" ::: "memory");
        __syncthreads();
        if (++slot == 3) slot = 0;
    }

    // Park 32x64 G sub-tile in smem, then gather pairs with head in range.
    float* sg = smem;                 // 8 KB
#pragma unroll
    for (int mi = 0; mi < 2; ++mi) {
        int row = mi * 16 + g;
        int col = warp_n * 8 + 2 * c;
        sg[row * 64 + col]           = acc[mi][0];
        sg[row * 64 + col + 1]       = acc[mi][1];
        sg[(row + 8) * 64 + col]     = acc[mi][2];
        sg[(row + 8) * 64 + col + 1] = acc[mi][3];
    }
    __syncthreads();

    float bv = bias[r];
    const float* Lb = g_L + (size_t)b * S_ * (2 * R_);
    const int* phb = ph + (b << 10);
    const int* ptb = pt + (b << 10);
#pragma unroll
    for (int i = 0; i < 4; ++i) {
        int p = tid + i * 256;
        int h = phb[p];
        unsigned dh = (unsigned)(h - s0g);
        if (dh < 32u) {
            int t = ptb[p];
            float sc = sg[dh * 64 + t] + Lb[h * 24 + r] + Lb[t * 24 + 12 + r] + bv;
            out[(size_t)((b << 10) + p) * R_ + r] = 1.f / (1.f + __expf(-sc));
        }
    }
}

// ---------------------------------------------------------------------------
// Launch.  Inputs in metadata order:
// 0 encoded f32 [8,512,256]   1 W_linear f32 [512,12]   2 b_linear f32 [12]
// 3 W_bilinear f32 [12,256,256]
// 4 span_starts i32 [8,64]    5 span_lens i32 [8,64]
// 6 pair_head i32 [8,1024]    7 pair_tail i32 [8,1024]
// Output f32 [8,1024,12].
// ---------------------------------------------------------------------------
extern "C" void kernel_launch(void* const* d_in, const int* in_sizes, int n_in,
                              void* d_out, int out_size) {
    const float* enc = (const float*)d_in[0];
    const float* Wl  = (const float*)d_in[1];
    const float* bl  = (const float*)d_in[2];
    const float* Wb  = (const float*)d_in[3];
    const int* sst   = (const int*)d_in[4];
    const int* sln   = (const int*)d_in[5];
    const int* ph    = (const int*)d_in[6];
    const int* pt    = (const int*)d_in[7];
    float* out = (float*)d_out;

    cudaFuncSetAttribute(gemm1_kernel,
                         cudaFuncAttributeMaxDynamicSharedMemorySize,
                         GEMM1_SMEM);
    cudaFuncSetAttribute(gemm2_kernel,
                         cudaFuncAttributeMaxDynamicSharedMemorySize,
                         GEMM2_SMEM);

    pool_kernel<<<B_ * S_, 256>>>(enc, Wl, sst, sln);
    split_wb_kernel<<<256, 256>>>(Wb);
    gemm1_kernel<<<dim3(N1 / 64, (B_ * S_) / 64), 256, GEMM1_SMEM>>>();
    gemm2_kernel<<<B_ * R_ * 2, 256, GEMM2_SMEM>>>(bl, ph, pt, out);
}